// round 11
// baseline (speedup 1.0000x reference)
#include <cuda_runtime.h>
#include <cuda_bf16.h>
#include <cstdint>

#define T_LEN 1024
#define B_N   128
#define H_N   256
#define G3    768

typedef unsigned long long u64;

// ---------------- scratch (device globals; no allocations allowed) ----------
__device__ float g_xg[(size_t)T_LEN * B_N * G3];      // [t][b][768]
__device__ float g_seq[(size_t)B_N * T_LEN * H_N];    // [b][t][256] layer-1 output
__device__ float g_hlast[B_N * H_N];                  // layer-2 final hidden

// ---------------- helpers ---------------------------------------------------
__device__ __forceinline__ float sigmoidf_(float x) {
    return __fdividef(1.0f, 1.0f + __expf(-x));
}
__device__ __forceinline__ float tanhf_(float x) {
    float ax = fabsf(x);
    float e  = __expf(-2.0f * ax);
    float t  = __fdividef(1.0f - e, 1.0f + e);
    return copysignf(t, x);
}
__device__ __forceinline__ void cluster_arrive_() {
    asm volatile("barrier.cluster.arrive.aligned;" ::: "memory");
}
__device__ __forceinline__ void cluster_wait_() {
    asm volatile("barrier.cluster.wait.aligned;" ::: "memory");
}
__device__ __forceinline__ void st_cluster_b16(uint32_t laddr, uint32_t rank, unsigned short v) {
    uint32_t raddr;
    asm volatile("mapa.shared::cluster.u32 %0, %1, %2;" : "=r"(raddr) : "r"(laddr), "r"(rank));
    asm volatile("st.shared::cluster.b16 [%0], %1;" :: "r"(raddr), "h"(v) : "memory");
}
__device__ __forceinline__ uint32_t smem_u32(const void* p) {
    return (uint32_t)__cvta_generic_to_shared(p);
}

// ---- mma.sync / ldmatrix wrappers (sm_80-era PTX; valid on sm_100) ----
__device__ __forceinline__ void ldmx4_(uint32_t* r, uint32_t addr) {
    asm volatile("ldmatrix.sync.aligned.m8n8.x4.shared.b16 {%0,%1,%2,%3}, [%4];"
                 : "=r"(r[0]), "=r"(r[1]), "=r"(r[2]), "=r"(r[3]) : "r"(addr));
}
__device__ __forceinline__ void ldmx2_(uint32_t* r, uint32_t addr) {
    asm volatile("ldmatrix.sync.aligned.m8n8.x2.shared.b16 {%0,%1}, [%2];"
                 : "=r"(r[0]), "=r"(r[1]) : "r"(addr));
}
__device__ __forceinline__ void mma16816_(float* c, const uint32_t* a, const uint32_t* b) {
    asm volatile(
        "mma.sync.aligned.m16n8k16.row.col.f32.bf16.bf16.f32 "
        "{%0,%1,%2,%3}, {%4,%5,%6,%7}, {%8,%9}, {%0,%1,%2,%3};"
        : "+f"(c[0]), "+f"(c[1]), "+f"(c[2]), "+f"(c[3])
        : "r"(a[0]), "r"(a[1]), "r"(a[2]), "r"(a[3]), "r"(b[0]), "r"(b[1]));
}

// ============================================================================
// Input projection GEMM via mma.sync (unchanged — measured good)
// ============================================================================
#define GT_ST   264
#define OFF_BIAS 0
#define OFF_AHI  256
#define OFF_ALO  (OFF_AHI + 128 * GT_ST * 2)
#define OFF_BHI  (OFF_ALO + 128 * GT_ST * 2)
#define OFF_BLO  (OFF_BHI + 64 * GT_ST * 2)
#define GT_SMEM  (OFF_BLO + 64 * GT_ST * 2)

__global__ void __launch_bounds__(256, 1) gemm_mma_kernel(
    const float* __restrict__ Ax,
    const float* __restrict__ W,
    const float* __restrict__ bias,
    int use_gseq)
{
    extern __shared__ char smc[];
    const uint32_t sb = smem_u32(smc);
    float* sBias = (float*)(smc + OFF_BIAS);
    __nv_bfloat16* sAhi = (__nv_bfloat16*)(smc + OFF_AHI);
    __nv_bfloat16* sAlo = (__nv_bfloat16*)(smc + OFF_ALO);
    __nv_bfloat16* sBhi = (__nv_bfloat16*)(smc + OFF_BHI);
    __nv_bfloat16* sBlo = (__nv_bfloat16*)(smc + OFF_BLO);

    const float* A = use_gseq ? g_seq : Ax;

    const int tid = threadIdx.x;
    const int nt = blockIdx.x;
    const int t  = blockIdx.y;

    if (tid < 64) sBias[tid] = bias[nt * 64 + tid];

#pragma unroll
    for (int i = 0; i < 32; i++) {
        int ch  = i * 256 + tid;
        int row = ch >> 6;
        int c4  = (ch & 63) << 2;
        float4 v = *(const float4*)(A + ((size_t)row * T_LEN + t) * H_N + c4);
        __nv_bfloat16 h0 = __float2bfloat16_rn(v.x);
        __nv_bfloat16 h1 = __float2bfloat16_rn(v.y);
        __nv_bfloat16 h2 = __float2bfloat16_rn(v.z);
        __nv_bfloat16 h3 = __float2bfloat16_rn(v.w);
        __nv_bfloat16 l0 = __float2bfloat16_rn(v.x - __bfloat162float(h0));
        __nv_bfloat16 l1 = __float2bfloat16_rn(v.y - __bfloat162float(h1));
        __nv_bfloat16 l2 = __float2bfloat16_rn(v.z - __bfloat162float(h2));
        __nv_bfloat16 l3 = __float2bfloat16_rn(v.w - __bfloat162float(h3));
        int o = row * GT_ST + c4;
        *(__nv_bfloat162*)(sAhi + o)     = __nv_bfloat162(h0, h1);
        *(__nv_bfloat162*)(sAhi + o + 2) = __nv_bfloat162(h2, h3);
        *(__nv_bfloat162*)(sAlo + o)     = __nv_bfloat162(l0, l1);
        *(__nv_bfloat162*)(sAlo + o + 2) = __nv_bfloat162(l2, l3);
    }
#pragma unroll
    for (int i = 0; i < 16; i++) {
        int ch  = i * 256 + tid;
        int row = ch >> 6;
        int c4  = (ch & 63) << 2;
        float4 v = *(const float4*)(W + ((size_t)(nt * 64 + row)) * H_N + c4);
        __nv_bfloat16 h0 = __float2bfloat16_rn(v.x);
        __nv_bfloat16 h1 = __float2bfloat16_rn(v.y);
        __nv_bfloat16 h2 = __float2bfloat16_rn(v.z);
        __nv_bfloat16 h3 = __float2bfloat16_rn(v.w);
        __nv_bfloat16 l0 = __float2bfloat16_rn(v.x - __bfloat162float(h0));
        __nv_bfloat16 l1 = __float2bfloat16_rn(v.y - __bfloat162float(h1));
        __nv_bfloat16 l2 = __float2bfloat16_rn(v.z - __bfloat162float(h2));
        __nv_bfloat16 l3 = __float2bfloat16_rn(v.w - __bfloat162float(h3));
        int o = row * GT_ST + c4;
        *(__nv_bfloat162*)(sBhi + o)     = __nv_bfloat162(h0, h1);
        *(__nv_bfloat162*)(sBhi + o + 2) = __nv_bfloat162(h2, h3);
        *(__nv_bfloat162*)(sBlo + o)     = __nv_bfloat162(l0, l1);
        *(__nv_bfloat162*)(sBlo + o + 2) = __nv_bfloat162(l2, l3);
    }
    __syncthreads();

    const int wid = tid >> 5;
    const int l   = tid & 31;
    const int m0  = wid << 4;

    const uint32_t aHi = sb + OFF_AHI + ((m0 + (l & 15)) * GT_ST + ((l >> 4) << 3)) * 2;
    const uint32_t aLo = sb + OFF_ALO + ((m0 + (l & 15)) * GT_ST + ((l >> 4) << 3)) * 2;
    const uint32_t bHi = sb + OFF_BHI + (((l & 7)) * GT_ST + (((l >> 3) & 1) << 3)) * 2;
    const uint32_t bLo = sb + OFF_BLO + (((l & 7)) * GT_ST + (((l >> 3) & 1) << 3)) * 2;

    float acc[8][4];
#pragma unroll
    for (int j = 0; j < 8; j++)
#pragma unroll
        for (int i = 0; i < 4; i++) acc[j][i] = 0.0f;

#pragma unroll 2
    for (int ks = 0; ks < 16; ks++) {
        uint32_t ah[4], al[4];
        ldmx4_(ah, aHi + ks * 32);
        ldmx4_(al, aLo + ks * 32);
#pragma unroll
        for (int j = 0; j < 8; j++) {
            uint32_t bh[2], bl[2];
            ldmx2_(bh, bHi + j * (8 * GT_ST * 2) + ks * 32);
            ldmx2_(bl, bLo + j * (8 * GT_ST * 2) + ks * 32);
            mma16816_(acc[j], ah, bh);
            mma16816_(acc[j], ah, bl);
            mma16816_(acc[j], al, bh);
        }
    }

    {
        const int gp = l >> 2;
        const int tg = l & 3;
        float* dst0 = g_xg + ((size_t)t * B_N + m0 + gp) * G3 + nt * 64;
        float* dst1 = dst0 + 8 * G3;
#pragma unroll
        for (int j = 0; j < 8; j++) {
            int c = j * 8 + 2 * tg;
            float b0 = sBias[c], b1 = sBias[c + 1];
            *(float2*)(dst0 + c) = make_float2(acc[j][0] + b0, acc[j][1] + b1);
            *(float2*)(dst1 + c) = make_float2(acc[j][2] + b0, acc[j][3] + b1);
        }
    }
}

// ============================================================================
// GRU recurrence v8 (tensor-core): 4-CTA clusters, 384 threads / 12 warps.
// Identical to v7 EXCEPT the MMA accumulator chain is split into 6
// independent sets (3 passes x 2 k-parities): dependency depth 48 -> 8,
// ILP 6, folded once per step.
// ============================================================================
#define R_ST      264
#define ROFF_ALO  0
#define ROFF_BHI  (192 * R_ST * 2)                  // [2 phases][8][264] bf16
#define ROFF_BLO  (ROFF_BHI + 2 * 8 * R_ST * 2)
#define ROFF_HG   (ROFF_BLO + 2 * 8 * R_ST * 2)     // [192][8] fp32
#define REC_SMEM  (ROFF_HG + 192 * 8 * 4)
#define B_PHASE   (8 * R_ST * 2)

__global__ void __cluster_dims__(4, 1, 1) __launch_bounds__(384, 1)
gru_rec_tc_kernel(const float* __restrict__ Whh,   // this layer's [768][256]
                  const float* __restrict__ bhh,   // this layer's [768]
                  int layer)
{
    extern __shared__ char smc[];
    const uint32_t sb = smem_u32(smc);
    __nv_bfloat16* sAlo = (__nv_bfloat16*)(smc + ROFF_ALO);
    float* sHG = (float*)(smc + ROFF_HG);

    const int tid  = threadIdx.x;               // 0..383
    const int rank = blockIdx.x & 3;
    const int b0   = (blockIdx.x >> 2) * 4;

    const int wid = tid >> 5;                   // 0..11, m-tile index
    const int l   = tid & 31;

    // ---- zero B buffers (both phases, hi+lo; covers batch-pad rows 4-7) ----
    for (int i = tid; i < (4 * B_PHASE) / 4; i += 384)
        *(uint32_t*)(smc + ROFF_BHI + 4 * i) = 0u;

    // ---- fill sAlo with W_hi (bf16), ldmatrix A-hi frags to regs ----
    for (int idx = tid; idx < 192 * 128; idx += 384) {
        int row = idx >> 7;
        int kp  = idx & 127;
        int jg  = ((row >> 6) << 8) + (rank << 6) + (row & 63);
        float2 v = *(const float2*)(Whh + (size_t)jg * H_N + 2 * kp);
        __nv_bfloat162 hv(__float2bfloat16_rn(v.x), __float2bfloat16_rn(v.y));
        *(__nv_bfloat162*)(sAlo + row * R_ST + 2 * kp) = hv;
    }
    __syncthreads();

    uint32_t ahi[16][4];
    {
        uint32_t base = sb + ROFF_ALO + (uint32_t)((16 * wid + (l & 15)) * R_ST + ((l >> 4) << 3)) * 2;
#pragma unroll
        for (int ks = 0; ks < 16; ks++)
            ldmx4_(ahi[ks], base + ks * 32);
    }
    __syncthreads();

    // ---- overwrite sAlo with W_lo ----
    for (int idx = tid; idx < 192 * 128; idx += 384) {
        int row = idx >> 7;
        int kp  = idx & 127;
        int jg  = ((row >> 6) << 8) + (rank << 6) + (row & 63);
        float2 v = *(const float2*)(Whh + (size_t)jg * H_N + 2 * kp);
        __nv_bfloat16 h0 = __float2bfloat16_rn(v.x);
        __nv_bfloat16 h1 = __float2bfloat16_rn(v.y);
        __nv_bfloat162 lv(__float2bfloat16_rn(v.x - __bfloat162float(h0)),
                          __float2bfloat16_rn(v.y - __bfloat162float(h1)));
        *(__nv_bfloat162*)(sAlo + row * R_ST + 2 * kp) = lv;
    }

    // ---- elementwise ownership: tid<256, one (unit, batch) each ----
    const int eu  = tid >> 2;                   // 0..63 (valid tid<256)
    const int eb  = tid & 3;
    const int eug = (rank << 6) + (eu & 63);
    float br_ = 0.f, bz_ = 0.f, bn_ = 0.f;
    if (tid < 256) {
        br_ = bhh[eug]; bz_ = bhh[256 + eug]; bn_ = bhh[512 + eug];
    }
    float hprev = 0.0f;

    // ldmatrix address bases (main loop)
    const uint32_t aloB = sb + ROFF_ALO + (uint32_t)((16 * wid + (l & 15)) * R_ST + ((l >> 4) << 3)) * 2;
    const uint32_t bOff = (uint32_t)((l & 7) * R_ST + (((l >> 3) & 1) << 3)) * 2;

    __syncthreads();
    cluster_arrive_();
    cluster_wait_();

    int p = 0;
    for (int t = 0; t < T_LEN; t++) {
        // ---- xg prefetch (before wait: latency hides in barrier skew) ----
        float xr = 0.f, xz = 0.f, xn = 0.f;
        if (tid < 256) {
            size_t xb = ((size_t)t * B_N + b0 + eb) * G3 + eug;
            xr = g_xg[xb]; xz = g_xg[xb + 256]; xn = g_xg[xb + 512];
        }
        if (t > 0) cluster_wait_();

        // ---- MMA phase: 6 independent accumulator chains (depth 8 each) ----
        const uint32_t bHi = sb + ROFF_BHI + p * B_PHASE + bOff;
        const uint32_t bLo = sb + ROFF_BLO + p * B_PHASE + bOff;
        float ca0[4] = {0.f, 0.f, 0.f, 0.f};   // ahi*bh, even ks
        float ca1[4] = {0.f, 0.f, 0.f, 0.f};   // ahi*bh, odd ks
        float cb0[4] = {0.f, 0.f, 0.f, 0.f};   // ahi*bl, even ks
        float cb1[4] = {0.f, 0.f, 0.f, 0.f};   // ahi*bl, odd ks
        float cc0[4] = {0.f, 0.f, 0.f, 0.f};   // alo*bh, even ks
        float cc1[4] = {0.f, 0.f, 0.f, 0.f};   // alo*bh, odd ks
#pragma unroll
        for (int kq = 0; kq < 8; kq++) {
            int ks0 = 2 * kq, ks1 = 2 * kq + 1;
            uint32_t bh0[2], bl0[2], al0[4], bh1[2], bl1[2], al1[4];
            ldmx2_(bh0, bHi + ks0 * 32);
            ldmx2_(bl0, bLo + ks0 * 32);
            ldmx4_(al0, aloB + ks0 * 32);
            ldmx2_(bh1, bHi + ks1 * 32);
            ldmx2_(bl1, bLo + ks1 * 32);
            ldmx4_(al1, aloB + ks1 * 32);
            mma16816_(ca0, ahi[ks0], bh0);
            mma16816_(cb0, ahi[ks0], bl0);
            mma16816_(cc0, al0, bh0);
            mma16816_(ca1, ahi[ks1], bh1);
            mma16816_(cb1, ahi[ks1], bl1);
            mma16816_(cc1, al1, bh1);
        }
        float c0[4];
#pragma unroll
        for (int i = 0; i < 4; i++)
            c0[i] = (ca0[i] + ca1[i]) + (cb0[i] + cb1[i]) + (cc0[i] + cc1[i]);

        // ---- stage D frags -> sHG[row][8] ----
        {
            int r0 = 16 * wid + (l >> 2);
            *(float2*)(sHG + r0 * 8 + 2 * (l & 3))       = make_float2(c0[0], c0[1]);
            *(float2*)(sHG + (r0 + 8) * 8 + 2 * (l & 3)) = make_float2(c0[2], c0[3]);
        }
        __syncthreads();

        // ---- elementwise + bf16 hi/lo DSMEM broadcast (single tranche) ----
        float hnew = 0.f;
        if (tid < 256) {
            const uint32_t bhiN = sb + ROFF_BHI + (1 - p) * B_PHASE;
            const uint32_t bloN = sb + ROFF_BLO + (1 - p) * B_PHASE;
            float hr = sHG[eu * 8 + eb] + br_;
            float hz = sHG[(64 + eu) * 8 + eb] + bz_;
            float hn = sHG[(128 + eu) * 8 + eb] + bn_;
            float r = sigmoidf_(xr + hr);
            float z = sigmoidf_(xz + hz);
            float n = tanhf_(xn + r * hn);
            hnew = (1.0f - z) * n + z * hprev;
            hprev = hnew;
            __nv_bfloat16 hb = __float2bfloat16_rn(hnew);
            unsigned short hu = *(unsigned short*)&hb;
            __nv_bfloat16 lb = __float2bfloat16_rn(hnew - __bfloat162float(hb));
            unsigned short lu = *(unsigned short*)&lb;
            uint32_t off = (uint32_t)(eb * R_ST + eug) * 2;
#pragma unroll
            for (uint32_t rr = 0; rr < 4; rr++) {
                st_cluster_b16(bhiN + off, rr, hu);
                st_cluster_b16(bloN + off, rr, lu);
            }
        }

        cluster_arrive_();   // release: publishes DSMEM bf16 h + frees sHG/sB[p]

        // global stores off the critical path
        if (tid < 256) {
            if (layer == 0) {
                g_seq[((size_t)(b0 + eb) * T_LEN + t) * H_N + eug] = hnew;
            } else if (t == T_LEN - 1) {
                g_hlast[(b0 + eb) * H_N + eug] = hnew;
            }
        }
        p ^= 1;
    }
    cluster_wait_();
}

// ============================================================================
// Final FC
// ============================================================================
__global__ void fc_kernel(const float* __restrict__ Wfc,
                          const float* __restrict__ bfc,
                          float* __restrict__ out)
{
    __shared__ float sh[H_N];
    const int b = blockIdx.x, n = threadIdx.x;
    sh[n] = g_hlast[b * H_N + n];
    __syncthreads();
    const float* w = Wfc + (size_t)n * H_N;
    float acc = 0.0f;
#pragma unroll 4
    for (int k = 0; k < H_N; k++) acc += sh[k] * w[k];
    out[b * H_N + n] = sigmoidf_(acc + bfc[n]);
}

// ============================================================================
extern "C" void kernel_launch(void* const* d_in, const int* in_sizes, int n_in,
                              void* d_out, int out_size)
{
    const float* x   = (const float*)d_in[0];
    const float* Wih = (const float*)d_in[1];
    const float* Whh = (const float*)d_in[2];
    const float* bih = (const float*)d_in[3];
    const float* bhh = (const float*)d_in[4];
    const float* Wfc = (const float*)d_in[5];
    const float* bfc = (const float*)d_in[6];
    float* out = (float*)d_out;

    cudaFuncSetAttribute(gemm_mma_kernel, cudaFuncAttributeMaxDynamicSharedMemorySize, GT_SMEM);
    cudaFuncSetAttribute(gru_rec_tc_kernel, cudaFuncAttributeMaxDynamicSharedMemorySize, REC_SMEM);

    dim3 ggrid(12, T_LEN);

    // layer 0
    gemm_mma_kernel<<<ggrid, 256, GT_SMEM>>>(x, Wih, bih, 0);
    gru_rec_tc_kernel<<<128, 384, REC_SMEM>>>(Whh, bhh, 0);
    // layer 1
    gemm_mma_kernel<<<ggrid, 256, GT_SMEM>>>(nullptr, Wih + (size_t)G3 * H_N, bih + G3, 1);
    gru_rec_tc_kernel<<<128, 384, REC_SMEM>>>(Whh + (size_t)G3 * H_N, bhh + G3, 1);
    // head
    fc_kernel<<<B_N, H_N>>>(Wfc, bfc, out);
}

// round 12
// speedup vs baseline: 1.1241x; 1.1241x over previous
#include <cuda_runtime.h>
#include <cuda_bf16.h>
#include <cstdint>

#define T_LEN 1024
#define B_N   128
#define H_N   256
#define G3    768

typedef unsigned long long u64;

// ---------------- scratch (device globals; no allocations allowed) ----------
__device__ float g_xg[(size_t)T_LEN * B_N * G3];      // [t][b][768]
__device__ float g_seq[(size_t)B_N * T_LEN * H_N];    // [b][t][256] layer-1 output
__device__ float g_hlast[B_N * H_N];                  // layer-2 final hidden

// ---------------- helpers ---------------------------------------------------
__device__ __forceinline__ float sigmoidf_(float x) {
    return __fdividef(1.0f, 1.0f + __expf(-x));
}
__device__ __forceinline__ float tanhf_(float x) {
    float ax = fabsf(x);
    float e  = __expf(-2.0f * ax);
    float t  = __fdividef(1.0f - e, 1.0f + e);
    return copysignf(t, x);
}
__device__ __forceinline__ void cluster_arrive_() {
    asm volatile("barrier.cluster.arrive.aligned;" ::: "memory");
}
__device__ __forceinline__ void cluster_wait_() {
    asm volatile("barrier.cluster.wait.aligned;" ::: "memory");
}
__device__ __forceinline__ void st_cluster_b16(uint32_t laddr, uint32_t rank, unsigned short v) {
    uint32_t raddr;
    asm volatile("mapa.shared::cluster.u32 %0, %1, %2;" : "=r"(raddr) : "r"(laddr), "r"(rank));
    asm volatile("st.shared::cluster.b16 [%0], %1;" :: "r"(raddr), "h"(v) : "memory");
}
__device__ __forceinline__ uint32_t smem_u32(const void* p) {
    return (uint32_t)__cvta_generic_to_shared(p);
}

// ---- mma.sync / ldmatrix wrappers (sm_80-era PTX; valid on sm_100) ----
__device__ __forceinline__ void ldmx4_(uint32_t* r, uint32_t addr) {
    asm volatile("ldmatrix.sync.aligned.m8n8.x4.shared.b16 {%0,%1,%2,%3}, [%4];"
                 : "=r"(r[0]), "=r"(r[1]), "=r"(r[2]), "=r"(r[3]) : "r"(addr));
}
__device__ __forceinline__ void ldmx2_(uint32_t* r, uint32_t addr) {
    asm volatile("ldmatrix.sync.aligned.m8n8.x2.shared.b16 {%0,%1}, [%2];"
                 : "=r"(r[0]), "=r"(r[1]) : "r"(addr));
}
__device__ __forceinline__ void mma16816_(float* c, const uint32_t* a, const uint32_t* b) {
    asm volatile(
        "mma.sync.aligned.m16n8k16.row.col.f32.bf16.bf16.f32 "
        "{%0,%1,%2,%3}, {%4,%5,%6,%7}, {%8,%9}, {%0,%1,%2,%3};"
        : "+f"(c[0]), "+f"(c[1]), "+f"(c[2]), "+f"(c[3])
        : "r"(a[0]), "r"(a[1]), "r"(a[2]), "r"(a[3]), "r"(b[0]), "r"(b[1]));
}

// ============================================================================
// Input projection GEMM via mma.sync (unchanged — measured good)
// ============================================================================
#define GT_ST   264
#define OFF_BIAS 0
#define OFF_AHI  256
#define OFF_ALO  (OFF_AHI + 128 * GT_ST * 2)
#define OFF_BHI  (OFF_ALO + 128 * GT_ST * 2)
#define OFF_BLO  (OFF_BHI + 64 * GT_ST * 2)
#define GT_SMEM  (OFF_BLO + 64 * GT_ST * 2)

__global__ void __launch_bounds__(256, 1) gemm_mma_kernel(
    const float* __restrict__ Ax,
    const float* __restrict__ W,
    const float* __restrict__ bias,
    int use_gseq)
{
    extern __shared__ char smc[];
    const uint32_t sb = smem_u32(smc);
    float* sBias = (float*)(smc + OFF_BIAS);
    __nv_bfloat16* sAhi = (__nv_bfloat16*)(smc + OFF_AHI);
    __nv_bfloat16* sAlo = (__nv_bfloat16*)(smc + OFF_ALO);
    __nv_bfloat16* sBhi = (__nv_bfloat16*)(smc + OFF_BHI);
    __nv_bfloat16* sBlo = (__nv_bfloat16*)(smc + OFF_BLO);

    const float* A = use_gseq ? g_seq : Ax;

    const int tid = threadIdx.x;
    const int nt = blockIdx.x;
    const int t  = blockIdx.y;

    if (tid < 64) sBias[tid] = bias[nt * 64 + tid];

#pragma unroll
    for (int i = 0; i < 32; i++) {
        int ch  = i * 256 + tid;
        int row = ch >> 6;
        int c4  = (ch & 63) << 2;
        float4 v = *(const float4*)(A + ((size_t)row * T_LEN + t) * H_N + c4);
        __nv_bfloat16 h0 = __float2bfloat16_rn(v.x);
        __nv_bfloat16 h1 = __float2bfloat16_rn(v.y);
        __nv_bfloat16 h2 = __float2bfloat16_rn(v.z);
        __nv_bfloat16 h3 = __float2bfloat16_rn(v.w);
        __nv_bfloat16 l0 = __float2bfloat16_rn(v.x - __bfloat162float(h0));
        __nv_bfloat16 l1 = __float2bfloat16_rn(v.y - __bfloat162float(h1));
        __nv_bfloat16 l2 = __float2bfloat16_rn(v.z - __bfloat162float(h2));
        __nv_bfloat16 l3 = __float2bfloat16_rn(v.w - __bfloat162float(h3));
        int o = row * GT_ST + c4;
        *(__nv_bfloat162*)(sAhi + o)     = __nv_bfloat162(h0, h1);
        *(__nv_bfloat162*)(sAhi + o + 2) = __nv_bfloat162(h2, h3);
        *(__nv_bfloat162*)(sAlo + o)     = __nv_bfloat162(l0, l1);
        *(__nv_bfloat162*)(sAlo + o + 2) = __nv_bfloat162(l2, l3);
    }
#pragma unroll
    for (int i = 0; i < 16; i++) {
        int ch  = i * 256 + tid;
        int row = ch >> 6;
        int c4  = (ch & 63) << 2;
        float4 v = *(const float4*)(W + ((size_t)(nt * 64 + row)) * H_N + c4);
        __nv_bfloat16 h0 = __float2bfloat16_rn(v.x);
        __nv_bfloat16 h1 = __float2bfloat16_rn(v.y);
        __nv_bfloat16 h2 = __float2bfloat16_rn(v.z);
        __nv_bfloat16 h3 = __float2bfloat16_rn(v.w);
        __nv_bfloat16 l0 = __float2bfloat16_rn(v.x - __bfloat162float(h0));
        __nv_bfloat16 l1 = __float2bfloat16_rn(v.y - __bfloat162float(h1));
        __nv_bfloat16 l2 = __float2bfloat16_rn(v.z - __bfloat162float(h2));
        __nv_bfloat16 l3 = __float2bfloat16_rn(v.w - __bfloat162float(h3));
        int o = row * GT_ST + c4;
        *(__nv_bfloat162*)(sBhi + o)     = __nv_bfloat162(h0, h1);
        *(__nv_bfloat162*)(sBhi + o + 2) = __nv_bfloat162(h2, h3);
        *(__nv_bfloat162*)(sBlo + o)     = __nv_bfloat162(l0, l1);
        *(__nv_bfloat162*)(sBlo + o + 2) = __nv_bfloat162(l2, l3);
    }
    __syncthreads();

    const int wid = tid >> 5;
    const int l   = tid & 31;
    const int m0  = wid << 4;

    const uint32_t aHi = sb + OFF_AHI + ((m0 + (l & 15)) * GT_ST + ((l >> 4) << 3)) * 2;
    const uint32_t aLo = sb + OFF_ALO + ((m0 + (l & 15)) * GT_ST + ((l >> 4) << 3)) * 2;
    const uint32_t bHi = sb + OFF_BHI + (((l & 7)) * GT_ST + (((l >> 3) & 1) << 3)) * 2;
    const uint32_t bLo = sb + OFF_BLO + (((l & 7)) * GT_ST + (((l >> 3) & 1) << 3)) * 2;

    float acc[8][4];
#pragma unroll
    for (int j = 0; j < 8; j++)
#pragma unroll
        for (int i = 0; i < 4; i++) acc[j][i] = 0.0f;

#pragma unroll 2
    for (int ks = 0; ks < 16; ks++) {
        uint32_t ah[4], al[4];
        ldmx4_(ah, aHi + ks * 32);
        ldmx4_(al, aLo + ks * 32);
#pragma unroll
        for (int j = 0; j < 8; j++) {
            uint32_t bh[2], bl[2];
            ldmx2_(bh, bHi + j * (8 * GT_ST * 2) + ks * 32);
            ldmx2_(bl, bLo + j * (8 * GT_ST * 2) + ks * 32);
            mma16816_(acc[j], ah, bh);
            mma16816_(acc[j], ah, bl);
            mma16816_(acc[j], al, bh);
        }
    }

    {
        const int gp = l >> 2;
        const int tg = l & 3;
        float* dst0 = g_xg + ((size_t)t * B_N + m0 + gp) * G3 + nt * 64;
        float* dst1 = dst0 + 8 * G3;
#pragma unroll
        for (int j = 0; j < 8; j++) {
            int c = j * 8 + 2 * tg;
            float b0 = sBias[c], b1 = sBias[c + 1];
            *(float2*)(dst0 + c) = make_float2(acc[j][0] + b0, acc[j][1] + b1);
            *(float2*)(dst1 + c) = make_float2(acc[j][2] + b0, acc[j][3] + b1);
        }
    }
}

// ============================================================================
// GRU recurrence v9 (tensor-core): 4-CTA clusters, 384 threads / 12 warps.
// PACKED-N scheme: B tile rows 0-3 = h_hi (4 batches), rows 4-7 = h_lo.
// 2 MMA passes (Whi*B, Wlo*B) cover all 4 split products (lo*lo free):
//   per warp/step: 16 ldmx2(B) + 16 ldmx4(Alo) + 32 mma  (was 32/16/48).
// Elementwise gathers cols b and b+4 from sHG. Rest identical to R9 base.
// ============================================================================
#define R_ST      264
#define ROFF_ALO  0
#define ROFF_B    (192 * R_ST * 2)                  // [2 phases][8][264] bf16
#define ROFF_HG   (ROFF_B + 2 * 8 * R_ST * 2)       // [192][8] fp32
#define REC_SMEM  (ROFF_HG + 192 * 8 * 4)
#define B_PHASE   (8 * R_ST * 2)

__global__ void __cluster_dims__(4, 1, 1) __launch_bounds__(384, 1)
gru_rec_tc_kernel(const float* __restrict__ Whh,   // this layer's [768][256]
                  const float* __restrict__ bhh,   // this layer's [768]
                  int layer)
{
    extern __shared__ char smc[];
    const uint32_t sb = smem_u32(smc);
    __nv_bfloat16* sAlo = (__nv_bfloat16*)(smc + ROFF_ALO);
    float* sHG = (float*)(smc + ROFF_HG);

    const int tid  = threadIdx.x;               // 0..383
    const int rank = blockIdx.x & 3;
    const int b0   = (blockIdx.x >> 2) * 4;

    const int wid = tid >> 5;                   // 0..11, m-tile index
    const int l   = tid & 31;

    // ---- zero combined B buffer (both phases; h=0 -> hi=lo=0) ----
    for (int i = tid; i < (2 * B_PHASE) / 4; i += 384)
        *(uint32_t*)(smc + ROFF_B + 4 * i) = 0u;

    // ---- fill sAlo with W_hi (bf16), ldmatrix A-hi frags to regs ----
    for (int idx = tid; idx < 192 * 128; idx += 384) {
        int row = idx >> 7;
        int kp  = idx & 127;
        int jg  = ((row >> 6) << 8) + (rank << 6) + (row & 63);
        float2 v = *(const float2*)(Whh + (size_t)jg * H_N + 2 * kp);
        __nv_bfloat162 hv(__float2bfloat16_rn(v.x), __float2bfloat16_rn(v.y));
        *(__nv_bfloat162*)(sAlo + row * R_ST + 2 * kp) = hv;
    }
    __syncthreads();

    uint32_t ahi[16][4];
    {
        uint32_t base = sb + ROFF_ALO + (uint32_t)((16 * wid + (l & 15)) * R_ST + ((l >> 4) << 3)) * 2;
#pragma unroll
        for (int ks = 0; ks < 16; ks++)
            ldmx4_(ahi[ks], base + ks * 32);
    }
    __syncthreads();

    // ---- overwrite sAlo with W_lo ----
    for (int idx = tid; idx < 192 * 128; idx += 384) {
        int row = idx >> 7;
        int kp  = idx & 127;
        int jg  = ((row >> 6) << 8) + (rank << 6) + (row & 63);
        float2 v = *(const float2*)(Whh + (size_t)jg * H_N + 2 * kp);
        __nv_bfloat16 h0 = __float2bfloat16_rn(v.x);
        __nv_bfloat16 h1 = __float2bfloat16_rn(v.y);
        __nv_bfloat162 lv(__float2bfloat16_rn(v.x - __bfloat162float(h0)),
                          __float2bfloat16_rn(v.y - __bfloat162float(h1)));
        *(__nv_bfloat162*)(sAlo + row * R_ST + 2 * kp) = lv;
    }

    // ---- elementwise ownership: tid<256, one (unit, batch) each ----
    const int eu  = tid >> 2;                   // 0..63 (valid tid<256)
    const int eb  = tid & 3;
    const int eug = (rank << 6) + (eu & 63);
    float br_ = 0.f, bz_ = 0.f, bn_ = 0.f;
    if (tid < 256) {
        br_ = bhh[eug]; bz_ = bhh[256 + eug]; bn_ = bhh[512 + eug];
    }
    float hprev = 0.0f;

    // ldmatrix address bases (main loop)
    const uint32_t aloB = sb + ROFF_ALO + (uint32_t)((16 * wid + (l & 15)) * R_ST + ((l >> 4) << 3)) * 2;
    const uint32_t bOff = (uint32_t)((l & 7) * R_ST + (((l >> 3) & 1) << 3)) * 2;

    __syncthreads();
    cluster_arrive_();
    cluster_wait_();

    int p = 0;
    for (int t = 0; t < T_LEN; t++) {
        // ---- xg prefetch (before wait: latency hides in barrier skew) ----
        float xr = 0.f, xz = 0.f, xn = 0.f;
        if (tid < 256) {
            size_t xb = ((size_t)t * B_N + b0 + eb) * G3 + eug;
            xr = g_xg[xb]; xz = g_xg[xb + 256]; xn = g_xg[xb + 512];
        }
        if (t > 0) cluster_wait_();

        // ---- MMA phase: 2 passes over combined B (hi cols 0-3, lo cols 4-7)
        const uint32_t bB = sb + ROFF_B + p * B_PHASE + bOff;
        float cH[4] = {0.f, 0.f, 0.f, 0.f};
        float cL[4] = {0.f, 0.f, 0.f, 0.f};
#pragma unroll
        for (int ks = 0; ks < 16; ks++) {
            uint32_t bf[2], al[4];
            ldmx2_(bf, bB + ks * 32);
            ldmx4_(al, aloB + ks * 32);
            mma16816_(cH, ahi[ks], bf);
            mma16816_(cL, al, bf);
        }
        float c0[4];
#pragma unroll
        for (int i = 0; i < 4; i++) c0[i] = cH[i] + cL[i];

        // ---- stage D frags -> sHG[row][8] ----
        {
            int r0 = 16 * wid + (l >> 2);
            *(float2*)(sHG + r0 * 8 + 2 * (l & 3))       = make_float2(c0[0], c0[1]);
            *(float2*)(sHG + (r0 + 8) * 8 + 2 * (l & 3)) = make_float2(c0[2], c0[3]);
        }
        __syncthreads();

        // ---- elementwise: gather hi-col (b) + lo-col (b+4), then gates ----
        float hnew = 0.f;
        if (tid < 256) {
            const uint32_t bN = sb + ROFF_B + (1 - p) * B_PHASE;
            float hr = sHG[eu * 8 + eb]         + sHG[eu * 8 + 4 + eb]         + br_;
            float hz = sHG[(64 + eu) * 8 + eb]  + sHG[(64 + eu) * 8 + 4 + eb]  + bz_;
            float hn = sHG[(128 + eu) * 8 + eb] + sHG[(128 + eu) * 8 + 4 + eb] + bn_;
            float r = sigmoidf_(xr + hr);
            float z = sigmoidf_(xz + hz);
            float n = tanhf_(xn + r * hn);
            hnew = (1.0f - z) * n + z * hprev;
            hprev = hnew;
            __nv_bfloat16 hb = __float2bfloat16_rn(hnew);
            unsigned short hu = *(unsigned short*)&hb;
            __nv_bfloat16 lb = __float2bfloat16_rn(hnew - __bfloat162float(hb));
            unsigned short lu = *(unsigned short*)&lb;
            uint32_t offH = (uint32_t)(eb * R_ST + eug) * 2;
            uint32_t offL = (uint32_t)((eb + 4) * R_ST + eug) * 2;
#pragma unroll
            for (uint32_t rr = 0; rr < 4; rr++) {
                st_cluster_b16(bN + offH, rr, hu);
                st_cluster_b16(bN + offL, rr, lu);
            }
        }

        cluster_arrive_();   // release: publishes DSMEM h + frees sHG/B[p]

        // global stores off the critical path
        if (tid < 256) {
            if (layer == 0) {
                g_seq[((size_t)(b0 + eb) * T_LEN + t) * H_N + eug] = hnew;
            } else if (t == T_LEN - 1) {
                g_hlast[(b0 + eb) * H_N + eug] = hnew;
            }
        }
        p ^= 1;
    }
    cluster_wait_();
}

// ============================================================================
// Final FC
// ============================================================================
__global__ void fc_kernel(const float* __restrict__ Wfc,
                          const float* __restrict__ bfc,
                          float* __restrict__ out)
{
    __shared__ float sh[H_N];
    const int b = blockIdx.x, n = threadIdx.x;
    sh[n] = g_hlast[b * H_N + n];
    __syncthreads();
    const float* w = Wfc + (size_t)n * H_N;
    float acc = 0.0f;
#pragma unroll 4
    for (int k = 0; k < H_N; k++) acc += sh[k] * w[k];
    out[b * H_N + n] = sigmoidf_(acc + bfc[n]);
}

// ============================================================================
extern "C" void kernel_launch(void* const* d_in, const int* in_sizes, int n_in,
                              void* d_out, int out_size)
{
    const float* x   = (const float*)d_in[0];
    const float* Wih = (const float*)d_in[1];
    const float* Whh = (const float*)d_in[2];
    const float* bih = (const float*)d_in[3];
    const float* bhh = (const float*)d_in[4];
    const float* Wfc = (const float*)d_in[5];
    const float* bfc = (const float*)d_in[6];
    float* out = (float*)d_out;

    cudaFuncSetAttribute(gemm_mma_kernel, cudaFuncAttributeMaxDynamicSharedMemorySize, GT_SMEM);
    cudaFuncSetAttribute(gru_rec_tc_kernel, cudaFuncAttributeMaxDynamicSharedMemorySize, REC_SMEM);

    dim3 ggrid(12, T_LEN);

    // layer 0
    gemm_mma_kernel<<<ggrid, 256, GT_SMEM>>>(x, Wih, bih, 0);
    gru_rec_tc_kernel<<<128, 384, REC_SMEM>>>(Whh, bhh, 0);
    // layer 1
    gemm_mma_kernel<<<ggrid, 256, GT_SMEM>>>(nullptr, Wih + (size_t)G3 * H_N, bih + G3, 1);
    gru_rec_tc_kernel<<<128, 384, REC_SMEM>>>(Whh + (size_t)G3 * H_N, bhh + G3, 1);
    // head
    fc_kernel<<<B_N, H_N>>>(Wfc, bfc, out);
}